// round 14
// baseline (speedup 1.0000x reference)
#include <cuda_runtime.h>
#include <math.h>

#define BS 16
#define NA 8400
#define NG 128
#define NC 80
#define TOPK 13
#define CAPW 640             // per-ROW candidate capacity (expected max ~425 + 10 sigma)
#define RPB 8                // rows per block (1 warp each)

#define GRIDB 20             // bins per dim
#define BINW_INV (1.0f/32.0f)
#define NBINS (GRIDB*GRIDB)
#define MAXSEG 8             // max covered bin-rows (box <=144px -> <=6)

#define EPS9 1e-9f
#define EPS7 1e-7f
#define FOUR_OVER_PI2 0.4052847345693511f

// ---- scratch (__device__ globals; no allocation allowed) ----
// INVARIANT: g_bincnt == 0 at kernel_launch entry. True at process start
// (static zero-init); kScan consumes the counts and re-zeroes them.
__device__ int                g_bincnt[NBINS];
__device__ int                g_off   [NBINS];           // fill cursors (set by kScan)
__device__ int                g_binstart[NBINS + 1];
__device__ int                g_csridx[NA];              // anchor index per CSR slot
__device__ int                g_firstg[BS * NA];         // min marked g (init BIG)
__device__ int                g_acnt  [BS * NA];         // mark count
__device__ unsigned long long g_bestpack[BS * NA];       // (al_bits<<32)|(127-g)
__device__ int                g_anyflag;

#define FIRSTG_INIT 0x40000000

// CIoU clipped to [0,inf); identical op order in KMAIN and K4.
__device__ __forceinline__ float ciou_clip(
    float b1x1, float b1y1, float b1x2, float b1y2,
    float b2x1, float b2y1, float b2x2, float b2y2)
{
    float iw = fminf(b1x2, b2x2) - fmaxf(b1x1, b2x1); iw = fmaxf(iw, 0.0f);
    float ih = fminf(b1y2, b2y2) - fmaxf(b1y1, b2y1); ih = fmaxf(ih, 0.0f);
    const float inter = iw * ih;
    const float w1 = b1x2 - b1x1, h1 = b1y2 - b1y1 + EPS7;
    const float w2 = b2x2 - b2x1, h2 = b2y2 - b2y1 + EPS7;
    const float uni = w1 * h1 + w2 * h2 - inter + EPS7;
    const float iou = inter / uni;
    const float cw = fmaxf(b1x2, b2x2) - fminf(b1x1, b2x1);
    const float ch = fmaxf(b1y2, b2y2) - fminf(b1y1, b2y1);
    const float c2 = cw * cw + ch * ch + EPS7;
    const float dx = b2x1 + b2x2 - b1x1 - b1x2;
    const float dy = b2y1 + b2y2 - b1y1 - b1y2;
    const float rho2 = (dx * dx + dy * dy) * 0.25f;
    const float dat = atanf(w2 / h2) - atanf(w1 / h1);
    const float v = FOUR_OVER_PI2 * dat * dat;
    const float alpha = v / (v - iou + (1.0f + EPS7));
    return fmaxf(iou - (rho2 / c2 + v * alpha), 0.0f);
}

__device__ __forceinline__ int bin_of(float x) {
    int b = (int)(x * BINW_INV);
    return (b < 0) ? 0 : ((b > GRIDB - 1) ? GRIDB - 1 : b);
}

// ============================================================
// K_COUNT: 132 blocks. Zero per-anchor state + anyflag; first
// NA threads count anchors per bin via GLOBAL atomics.
// ============================================================
#define CBLOCKS ((BS * NA + 1023) / 1024)     // 132
#define SCAN_WARPS ((NBINS + 31) / 32)        // 13

__global__ void kCount(const float* __restrict__ anc_points)
{
    const int i = blockIdx.x * 1024 + threadIdx.x;
    if (i < BS * NA) {
        g_firstg[i]   = FIRSTG_INIT;
        g_acnt[i]     = 0;
        g_bestpack[i] = 127ULL;     // pack(0.0f, g=0)
    }
    if (i == 0) g_anyflag = 0;
    if (i < NA) {
        const float2 p = reinterpret_cast<const float2*>(anc_points)[i];
        atomicAdd(&g_bincnt[bin_of(p.y) * GRIDB + bin_of(p.x)], 1);
    }
}

// ============================================================
// K_SCAN: one tiny block (512 thr): two-level parallel scan of
// the 400 counters -> g_binstart + g_off; re-zero g_bincnt.
// ============================================================
__global__ void kScan()
{
    const int tid  = threadIdx.x;   // 512
    const int wid  = tid >> 5;
    const int lane = tid & 31;
    __shared__ int s_wsum[SCAN_WARPS];

    int cnt = 0, inc = 0;
    if (tid < (SCAN_WARPS * 32)) {
        cnt = (tid < NBINS) ? g_bincnt[tid] : 0;
        inc = cnt;
#pragma unroll
        for (int off = 1; off < 32; off <<= 1) {
            const int n = __shfl_up_sync(0xffffffffu, inc, off);
            if (lane >= off) inc += n;
        }
        if (lane == 31) s_wsum[wid] = inc;
    }
    __syncthreads();
    if (wid == 0) {
        int ws = (lane < SCAN_WARPS) ? s_wsum[lane] : 0;
        int wi = ws;
#pragma unroll
        for (int off = 1; off < 32; off <<= 1) {
            const int n = __shfl_up_sync(0xffffffffu, wi, off);
            if (lane >= off) wi += n;
        }
        if (lane < SCAN_WARPS) s_wsum[lane] = wi - ws;   // exclusive warp offset
    }
    __syncthreads();
    if (tid < NBINS) {
        const int excl = (inc - cnt) + s_wsum[wid];
        g_binstart[tid] = excl;
        g_off[tid]      = excl;
        g_bincnt[tid]   = 0;        // restore invariant (counts consumed)
    }
    if (tid == 0) g_binstart[NBINS] = NA;
}

// ============================================================
// K_FILL: global atomic cursors (order-invariant consumers).
// ============================================================
__global__ void kFill(const float* __restrict__ anc_points)
{
    const int a = blockIdx.x * 1024 + threadIdx.x;
    if (a >= NA) return;
    const float2 p = reinterpret_cast<const float2*>(anc_points)[a];
    const int bin = bin_of(p.y) * GRIDB + bin_of(p.x);
    const int q = atomicAdd(&g_off[bin], 1);
    g_csridx[q] = a;
}

// ============================================================
// K_MAIN: ONE WARP per (b,g) row; 8 rows per 256-thread block.
// Ballot-compacted candidates as packed u64 keys
// ((val_bits<<32)|~a -> u64 max == (max val, min idx)), then
// per-warp top-13 with shuffle-only reduction. No block
// barriers; all marking ops order-invariant -> deterministic.
// ============================================================
__global__ void kmain(const float* __restrict__ pd_scores,
                      const float* __restrict__ pd_bboxes,
                      const int*   __restrict__ gt_labels,
                      const float* __restrict__ gt_bboxes,
                      const float* __restrict__ gt_mask,
                      const float* __restrict__ anc_points)
{
    const int wid  = threadIdx.x >> 5;       // 0..7
    const int lane = threadIdx.x & 31;
    const int row  = blockIdx.x * RPB + wid;  // b*NG + g
    const int b = row >> 7;
    const int g = row & (NG - 1);

    __shared__ unsigned long long s_key[RPB][CAPW];   // 40 KB
    __shared__ int s_seg_s[RPB][MAXSEG];
    __shared__ int s_seg_p[RPB][MAXSEG + 1];

    const float msk = gt_mask[row];           // same addr across warp: broadcast
    if (msk <= 0.0f) return;                  // warp-uniform exit

    const float4 gbb = reinterpret_cast<const float4*>(gt_bboxes)[(size_t)b * NG + g];
    int lbl = gt_labels[row];
    lbl = (lbl < 0) ? 0 : ((lbl >= NC) ? NC - 1 : lbl);

    if (lane == 0) {
        const int bx0 = bin_of(gbb.x), bx1 = bin_of(gbb.z);
        const int by0 = bin_of(gbb.y), by1 = bin_of(gbb.w);
        int acc = 0, ns = 0;
        for (int by = by0; by <= by1 && ns < MAXSEG; by++, ns++) {
            const int s = g_binstart[by * GRIDB + bx0];
            const int e = g_binstart[by * GRIDB + bx1 + 1];
            s_seg_s[wid][ns] = s;
            s_seg_p[wid][ns] = acc;
            acc += e - s;
        }
        for (int k2 = ns; k2 <= MAXSEG; k2++) s_seg_p[wid][k2] = acc;
    }
    __syncwarp();

    const int total = s_seg_p[wid][MAXSEG];
    const float2* anc2 = reinterpret_cast<const float2*>(anc_points);
    int cnt = 0;                              // warp-uniform

    for (int t0 = 0; t0 < total; t0 += 32) {
        const int t = t0 + lane;
        const bool valid = (t < total);
        float al = 0.0f;
        int a = 0;
        if (valid) {
            int r = 0;
#pragma unroll
            for (int k2 = 1; k2 < MAXSEG; k2++)
                if (t >= s_seg_p[wid][k2]) r = k2;
            const int j = s_seg_s[wid][r] + (t - s_seg_p[wid][r]);
            a = g_csridx[j];
            const float2 p = anc2[a];
            const float d0 = p.x - gbb.x, d1 = p.y - gbb.y;
            const float d2 = gbb.z - p.x, d3 = gbb.w - p.y;
            const float dmin = fminf(fminf(d0, d1), fminf(d2, d3));
            if (dmin > EPS9) {
                const float4 pb = reinterpret_cast<const float4*>(pd_bboxes)[(size_t)b * NA + a];
                const float io = ciou_clip(pb.x, pb.y, pb.z, pb.w,
                                           gbb.x, gbb.y, gbb.z, gbb.w);
                const float sc = pd_scores[((size_t)b * NA + a) * NC + lbl];
                const float i2 = io * io;
                al = sc * (i2 * i2 * i2) * msk;
                if (al > 0.0f) {
                    const unsigned long long pk =
                        ((unsigned long long)__float_as_uint(al) << 32) |
                        (unsigned long long)(127 - g);
                    atomicMax(&g_bestpack[b * NA + a], pk);
                }
            }
        }
        const bool cand = valid && (al > EPS9);
        const unsigned ball = __ballot_sync(0xffffffffu, cand);
        if (cand) {
            const int slot = cnt + __popc(ball & ((1u << lane) - 1u));
            if (slot < CAPW)
                s_key[wid][slot] =
                    ((unsigned long long)__float_as_uint(al) << 32) |
                    (unsigned long long)(~(unsigned)a);
        }
        cnt += __popc(ball);
    }
    __syncwarp();

    if (cnt > CAPW) cnt = CAPW;
    const int kmax = (TOPK < cnt) ? TOPK : cnt;

    for (int k = 0; k < kmax; k++) {
        unsigned long long bk = 0ULL;
        int bslot = -1;
        for (int i = lane; i < cnt; i += 32) {
            const unsigned long long key = s_key[wid][i];
            if (key > bk) { bk = key; bslot = i; }
        }
#pragma unroll
        for (int off = 16; off > 0; off >>= 1) {
            const unsigned long long ok = __shfl_down_sync(0xffffffffu, bk, off);
            const int os = __shfl_down_sync(0xffffffffu, bslot, off);
            if (ok > bk) { bk = ok; bslot = os; }
        }
        bslot = __shfl_sync(0xffffffffu, bslot, 0);
        if (lane == 0 && bslot >= 0) {    // keys are nonzero (al > EPS9)
            const int a = (int)(~(unsigned)(bk & 0xFFFFFFFFULL));
            atomicMin(&g_firstg[b * NA + a], g);
            const int old = atomicAdd(&g_acnt[b * NA + a], 1);
            if (old > 0) g_anyflag = 1;
            s_key[wid][bslot] = 0ULL;
        }
        __syncwarp();
    }
}

// ============================================================
// K4: per-anchor resolution + ALL outputs (fused; score write
// via smem staging, streaming stores).
// ============================================================
__global__ void k4_final(const int*   __restrict__ gt_labels,
                         const float* __restrict__ gt_bboxes,
                         const float* __restrict__ pd_bboxes,
                         const float* __restrict__ pd_scores,
                         const float* __restrict__ anc_points,
                         const float* __restrict__ gt_mask,
                         float* __restrict__ out)
{
    const int tid = threadIdx.x;                       // 256
    const int i   = blockIdx.x * 256 + tid;            // exact grid
    const int b   = i / NA;
    const int a   = i - b * NA;

    const int flag = g_anyflag;
    const int conf = (g_acnt[i] > 1);
    const int best = 127 - (int)(g_bestpack[i] & 0xFFULL);
    const int fg   = g_firstg[i];
    const int g0   = (fg >= FIRSTG_INIT) ? -1 : fg;

    int gA = -1, gB = -1; float vA = 0.0f, vB = 0.0f;
    if (flag) {
        if (!conf) {
            if (g0 < 0)          { gA = best; vA = 1.0f; }
            else if (g0 == best) { gA = g0;   vA = 2.0f; }
            else if (g0 < best)  { gA = g0; vA = 1.0f; gB = best; vB = 1.0f; }
            else                 { gA = best; vA = 1.0f; gB = g0; vB = 1.0f; }
        }
    } else {
        if (g0 >= 0) { gA = g0; vA = 1.0f; }
    }

    int tgt = 0;
    const int anyv = (gA >= 0);
    if (gA >= 0) tgt = gA;

    float maxamf = 0.0f, maxiou = 0.0f;
    if (anyv) {
        const float4 pb = reinterpret_cast<const float4*>(pd_bboxes)[(size_t)b * NA + a];
        const float ax = anc_points[a * 2 + 0];
        const float ay = anc_points[a * 2 + 1];
#pragma unroll
        for (int c = 0; c < 2; c++) {
            const int gc = (c == 0) ? gA : gB;
            const float vc = (c == 0) ? vA : vB;
            if (gc < 0) continue;
            const float4 gbb = reinterpret_cast<const float4*>(gt_bboxes)[(size_t)b * NG + gc];
            const float io = ciou_clip(pb.x, pb.y, pb.z, pb.w, gbb.x, gbb.y, gbb.z, gbb.w);
            int l = gt_labels[(size_t)b * NG + gc];
            l = (l < 0) ? 0 : ((l >= NC) ? NC - 1 : l);
            const float sc = pd_scores[((size_t)b * NA + a) * NC + l];
            const float d0 = ax - gbb.x, d1 = ay - gbb.y;
            const float d2 = gbb.z - ax, d3 = gbb.w - ay;
            const float dmin = fminf(fminf(d0, d1), fminf(d2, d3));
            const float mp = (dmin > EPS9) ? gt_mask[(size_t)b * NG + gc] : 0.0f;
            const float i2 = io * io;
            const float al = sc * (i2 * i2 * i2) * mp;
            maxamf = fmaxf(maxamf, al * vc);
            maxiou = fmaxf(maxiou, io * vc);
        }
    }
    const float norm = (maxamf * maxamf) / (maxiou + 1e-9f);
    const int   cls  = gt_labels[(size_t)b * NG + tgt];

    const size_t N1 = (size_t)BS * NA;
    out[i] = (float)cls;
    reinterpret_cast<float4*>(out + N1)[i] =
        reinterpret_cast<const float4*>(gt_bboxes)[(size_t)b * NG + tgt];
    const size_t off_mask = N1 * 5 + N1 * (size_t)NC;
    out[off_mask + i]      = anyv ? 1.0f : 0.0f;
    out[off_mask + N1 + i] = norm;

    // coalesced one-hot score write via smem staging; streaming stores
    __shared__ int   s_cls[256];
    __shared__ float s_nrm[256];
    s_cls[tid] = cls;
    s_nrm[tid] = norm;
    __syncthreads();
    float4* sco4 = reinterpret_cast<float4*>(out + N1 * 5 + (size_t)blockIdx.x * 256 * NC);
    for (int idx = tid; idx < 256 * (NC / 4); idx += 256) {
        const int al = idx / (NC / 4);
        const int q  = idx - al * (NC / 4);
        const int c0 = q * 4;
        const int cl = s_cls[al];
        const float nv = s_nrm[al];
        float4 w = make_float4(0.0f, 0.0f, 0.0f, 0.0f);
        if (cl == c0)     w.x = nv;
        if (cl == c0 + 1) w.y = nv;
        if (cl == c0 + 2) w.z = nv;
        if (cl == c0 + 3) w.w = nv;
        __stcs(sco4 + idx, w);
    }
}

// ============================================================
extern "C" void kernel_launch(void* const* d_in, const int* in_sizes, int n_in,
                              void* d_out, int out_size)
{
    const float* pd_scores = (const float*)d_in[0];
    const float* pd_bboxes = (const float*)d_in[1];
    const float* anc       = (const float*)d_in[2];
    const int*   gl        = (const int*)d_in[3];
    const float* gb        = (const float*)d_in[4];
    const float* gm        = (const float*)d_in[5];
    float* out = (float*)d_out;

    kCount<<<CBLOCKS, 1024>>>(anc);
    kScan<<<1, 512>>>();
    kFill<<<(NA + 1023) / 1024, 1024>>>(anc);
    kmain<<<(BS * NG) / RPB, 256>>>(pd_scores, pd_bboxes, gl, gb, gm, anc);
    k4_final<<<(BS * NA) / 256, 256>>>(gl, gb, pd_bboxes, pd_scores, anc, gm, out);
}

// round 15
// speedup vs baseline: 1.4034x; 1.4034x over previous
#include <cuda_runtime.h>
#include <math.h>

#define BS 16
#define NA 8400
#define NG 128
#define NC 80
#define TOPK 13
#define CAPC 1024            // per-row candidate capacity (expected max ~425)

#define GRIDB 20             // bins per dim
#define BINW_INV (1.0f/32.0f)
#define NBINS (GRIDB*GRIDB)
#define MAXSEG 8             // max covered bin-rows (box <=144px -> <=6)

#define EPS9 1e-9f
#define EPS7 1e-7f
#define FOUR_OVER_PI2 0.4052847345693511f

// ---- scratch (__device__ globals; no allocation allowed) ----
// INVARIANT: g_bincnt == 0 at kernel_launch entry. True at process start
// (static zero-init); kScan consumes the counts and re-zeroes them.
__device__ int                g_bincnt[NBINS];
__device__ int                g_off   [NBINS];           // fill cursors (set by kScan)
__device__ int                g_binstart[NBINS + 1];
__device__ int                g_csridx[NA];              // anchor index per CSR slot
__device__ int                g_firstg[BS * NA];         // min marked g (init BIG)
__device__ int                g_acnt  [BS * NA];         // mark count
__device__ unsigned long long g_bestpack[BS * NA];       // (al_bits<<32)|(127-g)
__device__ int                g_anyflag;

#define FIRSTG_INIT 0x40000000

// CIoU clipped to [0,inf); identical op order in KMAIN and K4.
__device__ __forceinline__ float ciou_clip(
    float b1x1, float b1y1, float b1x2, float b1y2,
    float b2x1, float b2y1, float b2x2, float b2y2)
{
    float iw = fminf(b1x2, b2x2) - fmaxf(b1x1, b2x1); iw = fmaxf(iw, 0.0f);
    float ih = fminf(b1y2, b2y2) - fmaxf(b1y1, b2y1); ih = fmaxf(ih, 0.0f);
    const float inter = iw * ih;
    const float w1 = b1x2 - b1x1, h1 = b1y2 - b1y1 + EPS7;
    const float w2 = b2x2 - b2x1, h2 = b2y2 - b2y1 + EPS7;
    const float uni = w1 * h1 + w2 * h2 - inter + EPS7;
    const float iou = inter / uni;
    const float cw = fmaxf(b1x2, b2x2) - fminf(b1x1, b2x1);
    const float ch = fmaxf(b1y2, b2y2) - fminf(b1y1, b2y1);
    const float c2 = cw * cw + ch * ch + EPS7;
    const float dx = b2x1 + b2x2 - b1x1 - b1x2;
    const float dy = b2y1 + b2y2 - b1y1 - b1y2;
    const float rho2 = (dx * dx + dy * dy) * 0.25f;
    const float dat = atanf(w2 / h2) - atanf(w1 / h1);
    const float v = FOUR_OVER_PI2 * dat * dat;
    const float alpha = v / (v - iou + (1.0f + EPS7));
    return fmaxf(iou - (rho2 / c2 + v * alpha), 0.0f);
}

__device__ __forceinline__ int bin_of(float x) {
    int b = (int)(x * BINW_INV);
    return (b < 0) ? 0 : ((b > GRIDB - 1) ? GRIDB - 1 : b);
}

// ============================================================
// K_COUNT: 132 blocks. Zero per-anchor state + anyflag; first
// NA threads count anchors per bin via GLOBAL atomics.
// ============================================================
#define CBLOCKS ((BS * NA + 1023) / 1024)     // 132
#define SCAN_WARPS ((NBINS + 31) / 32)        // 13

__global__ void kCount(const float* __restrict__ anc_points)
{
    const int i = blockIdx.x * 1024 + threadIdx.x;
    if (i < BS * NA) {
        g_firstg[i]   = FIRSTG_INIT;
        g_acnt[i]     = 0;
        g_bestpack[i] = 127ULL;     // pack(0.0f, g=0)
    }
    if (i == 0) g_anyflag = 0;
    if (i < NA) {
        const float2 p = reinterpret_cast<const float2*>(anc_points)[i];
        atomicAdd(&g_bincnt[bin_of(p.y) * GRIDB + bin_of(p.x)], 1);
    }
}

// ============================================================
// K_SCAN: one tiny block (512 thr): two-level parallel scan of
// the 400 counters -> g_binstart + g_off; re-zero g_bincnt.
// ============================================================
__global__ void kScan()
{
    const int tid  = threadIdx.x;   // 512
    const int wid  = tid >> 5;
    const int lane = tid & 31;
    __shared__ int s_wsum[SCAN_WARPS];

    int cnt = 0, inc = 0;
    if (tid < (SCAN_WARPS * 32)) {
        cnt = (tid < NBINS) ? g_bincnt[tid] : 0;
        inc = cnt;
#pragma unroll
        for (int off = 1; off < 32; off <<= 1) {
            const int n = __shfl_up_sync(0xffffffffu, inc, off);
            if (lane >= off) inc += n;
        }
        if (lane == 31) s_wsum[wid] = inc;
    }
    __syncthreads();
    if (wid == 0) {
        int ws = (lane < SCAN_WARPS) ? s_wsum[lane] : 0;
        int wi = ws;
#pragma unroll
        for (int off = 1; off < 32; off <<= 1) {
            const int n = __shfl_up_sync(0xffffffffu, wi, off);
            if (lane >= off) wi += n;
        }
        if (lane < SCAN_WARPS) s_wsum[lane] = wi - ws;   // exclusive warp offset
    }
    __syncthreads();
    if (tid < NBINS) {
        const int excl = (inc - cnt) + s_wsum[wid];
        g_binstart[tid] = excl;
        g_off[tid]      = excl;
        g_bincnt[tid]   = 0;        // restore invariant (counts consumed)
    }
    if (tid == 0) g_binstart[NBINS] = NA;
}

// ============================================================
// K_FILL: global atomic cursors (order-invariant consumers).
// ============================================================
__global__ void kFill(const float* __restrict__ anc_points)
{
    const int a = blockIdx.x * 1024 + threadIdx.x;
    if (a >= NA) return;
    const float2 p = reinterpret_cast<const float2*>(anc_points)[a];
    const int bin = bin_of(p.y) * GRIDB + bin_of(p.x);
    const int q = atomicAdd(&g_off[bin], 1);
    g_csridx[q] = a;
}

// ============================================================
// K_MAIN: one block (128 thr) per (b,g) row. Flattened segment
// gather into packed u64 keys ((al_bits<<32)|~a); warp-0 top-13
// via u64 max (== max val, min anchor idx — lax.top_k order).
// All marking ops order-invariant -> deterministic on replay.
// 128 threads -> ~11 blocks/SM resident -> ~1.3 waves.
// ============================================================
__global__ void kmain(const float* __restrict__ pd_scores,
                      const float* __restrict__ pd_bboxes,
                      const int*   __restrict__ gt_labels,
                      const float* __restrict__ gt_bboxes,
                      const float* __restrict__ gt_mask,
                      const float* __restrict__ anc_points)
{
    const int row = blockIdx.x;          // b*NG + g
    const int tid = threadIdx.x;         // 128
    const int b = row >> 7;
    const int g = row & (NG - 1);

    __shared__ unsigned long long s_key[CAPC];   // 8 KB
    __shared__ int   s_cnt;
    __shared__ int   s_seg_s[MAXSEG];
    __shared__ int   s_seg_p[MAXSEG + 1];
    __shared__ float4 s_box;
    __shared__ float  s_msk;
    __shared__ int    s_lbl;

    if (tid == 0) {
        s_cnt = 0;
        s_box = reinterpret_cast<const float4*>(gt_bboxes)[(size_t)b * NG + g];
        s_msk = gt_mask[row];
        int l = gt_labels[row];
        s_lbl = (l < 0) ? 0 : ((l >= NC) ? NC - 1 : l);
        const float4 bb = s_box;
        const int bx0 = bin_of(bb.x), bx1 = bin_of(bb.z);
        const int by0 = bin_of(bb.y), by1 = bin_of(bb.w);
        int acc = 0, ns = 0;
        for (int by = by0; by <= by1 && ns < MAXSEG; by++, ns++) {
            const int s = g_binstart[by * GRIDB + bx0];
            const int e = g_binstart[by * GRIDB + bx1 + 1];
            s_seg_s[ns] = s;
            s_seg_p[ns] = acc;
            acc += e - s;
        }
        for (int k2 = ns; k2 <= MAXSEG; k2++) s_seg_p[k2] = acc;
    }
    __syncthreads();

    const float msk = s_msk;
    if (msk <= 0.0f) return;

    const float4 gbb = s_box;
    const int lbl = s_lbl;
    const int total = s_seg_p[MAXSEG];
    const float2* anc2 = reinterpret_cast<const float2*>(anc_points);

    for (int t = tid; t < total; t += 128) {
        int r = 0;
#pragma unroll
        for (int k2 = 1; k2 < MAXSEG; k2++)
            if (t >= s_seg_p[k2]) r = k2;
        const int j = s_seg_s[r] + (t - s_seg_p[r]);

        const int a = g_csridx[j];
        const float2 p = anc2[a];
        const float d0 = p.x - gbb.x, d1 = p.y - gbb.y;
        const float d2 = gbb.z - p.x, d3 = gbb.w - p.y;
        const float dmin = fminf(fminf(d0, d1), fminf(d2, d3));
        if (dmin > EPS9) {
            const float4 pb = reinterpret_cast<const float4*>(pd_bboxes)[(size_t)b * NA + a];
            const float io = ciou_clip(pb.x, pb.y, pb.z, pb.w,
                                       gbb.x, gbb.y, gbb.z, gbb.w);
            const float sc = pd_scores[((size_t)b * NA + a) * NC + lbl];
            const float i2 = io * io;
            const float al = sc * (i2 * i2 * i2) * msk;
            if (al > 0.0f) {
                const unsigned long long pk =
                    ((unsigned long long)__float_as_uint(al) << 32) |
                    (unsigned long long)(127 - g);
                atomicMax(&g_bestpack[b * NA + a], pk);
            }
            if (al > EPS9) {
                const int pIdx = atomicAdd(&s_cnt, 1);
                if (pIdx < CAPC)
                    s_key[pIdx] =
                        ((unsigned long long)__float_as_uint(al) << 32) |
                        (unsigned long long)(~(unsigned)a);
            }
        }
    }
    __syncthreads();

    if (tid >= 32) return;               // warps 1..3 done; warp 0 does top-k

    int cnt = s_cnt;
    if (cnt > CAPC) cnt = CAPC;
    const int kmax = (TOPK < cnt) ? TOPK : cnt;

    for (int k = 0; k < kmax; k++) {
        unsigned long long bk = 0ULL;
        int bslot = -1;
        for (int i = tid; i < cnt; i += 32) {
            const unsigned long long key = s_key[i];
            if (key > bk) { bk = key; bslot = i; }
        }
#pragma unroll
        for (int off = 16; off > 0; off >>= 1) {
            const unsigned long long ok = __shfl_down_sync(0xffffffffu, bk, off);
            const int os = __shfl_down_sync(0xffffffffu, bslot, off);
            if (ok > bk) { bk = ok; bslot = os; }
        }
        bslot = __shfl_sync(0xffffffffu, bslot, 0);
        bk    = __shfl_sync(0xffffffffu, bk, 0);
        if (tid == 0 && bslot >= 0) {     // keys nonzero (al > EPS9)
            const int a = (int)(~(unsigned)(bk & 0xFFFFFFFFULL));
            atomicMin(&g_firstg[b * NA + a], g);
            const int old = atomicAdd(&g_acnt[b * NA + a], 1);
            if (old > 0) g_anyflag = 1;
            s_key[bslot] = 0ULL;
        }
        __syncwarp();
    }
}

// ============================================================
// K4: per-anchor resolution + ALL outputs (fused; score write
// via smem staging, streaming stores).
// ============================================================
__global__ void k4_final(const int*   __restrict__ gt_labels,
                         const float* __restrict__ gt_bboxes,
                         const float* __restrict__ pd_bboxes,
                         const float* __restrict__ pd_scores,
                         const float* __restrict__ anc_points,
                         const float* __restrict__ gt_mask,
                         float* __restrict__ out)
{
    const int tid = threadIdx.x;                       // 256
    const int i   = blockIdx.x * 256 + tid;            // exact grid
    const int b   = i / NA;
    const int a   = i - b * NA;

    const int flag = g_anyflag;
    const int conf = (g_acnt[i] > 1);
    const int best = 127 - (int)(g_bestpack[i] & 0xFFULL);
    const int fg   = g_firstg[i];
    const int g0   = (fg >= FIRSTG_INIT) ? -1 : fg;

    int gA = -1, gB = -1; float vA = 0.0f, vB = 0.0f;
    if (flag) {
        if (!conf) {
            if (g0 < 0)          { gA = best; vA = 1.0f; }
            else if (g0 == best) { gA = g0;   vA = 2.0f; }
            else if (g0 < best)  { gA = g0; vA = 1.0f; gB = best; vB = 1.0f; }
            else                 { gA = best; vA = 1.0f; gB = g0; vB = 1.0f; }
        }
    } else {
        if (g0 >= 0) { gA = g0; vA = 1.0f; }
    }

    int tgt = 0;
    const int anyv = (gA >= 0);
    if (gA >= 0) tgt = gA;

    float maxamf = 0.0f, maxiou = 0.0f;
    if (anyv) {
        const float4 pb = reinterpret_cast<const float4*>(pd_bboxes)[(size_t)b * NA + a];
        const float ax = anc_points[a * 2 + 0];
        const float ay = anc_points[a * 2 + 1];
#pragma unroll
        for (int c = 0; c < 2; c++) {
            const int gc = (c == 0) ? gA : gB;
            const float vc = (c == 0) ? vA : vB;
            if (gc < 0) continue;
            const float4 gbb = reinterpret_cast<const float4*>(gt_bboxes)[(size_t)b * NG + gc];
            const float io = ciou_clip(pb.x, pb.y, pb.z, pb.w, gbb.x, gbb.y, gbb.z, gbb.w);
            int l = gt_labels[(size_t)b * NG + gc];
            l = (l < 0) ? 0 : ((l >= NC) ? NC - 1 : l);
            const float sc = pd_scores[((size_t)b * NA + a) * NC + l];
            const float d0 = ax - gbb.x, d1 = ay - gbb.y;
            const float d2 = gbb.z - ax, d3 = gbb.w - ay;
            const float dmin = fminf(fminf(d0, d1), fminf(d2, d3));
            const float mp = (dmin > EPS9) ? gt_mask[(size_t)b * NG + gc] : 0.0f;
            const float i2 = io * io;
            const float al = sc * (i2 * i2 * i2) * mp;
            maxamf = fmaxf(maxamf, al * vc);
            maxiou = fmaxf(maxiou, io * vc);
        }
    }
    const float norm = (maxamf * maxamf) / (maxiou + 1e-9f);
    const int   cls  = gt_labels[(size_t)b * NG + tgt];

    const size_t N1 = (size_t)BS * NA;
    out[i] = (float)cls;
    reinterpret_cast<float4*>(out + N1)[i] =
        reinterpret_cast<const float4*>(gt_bboxes)[(size_t)b * NG + tgt];
    const size_t off_mask = N1 * 5 + N1 * (size_t)NC;
    out[off_mask + i]      = anyv ? 1.0f : 0.0f;
    out[off_mask + N1 + i] = norm;

    // coalesced one-hot score write via smem staging; streaming stores
    __shared__ int   s_cls[256];
    __shared__ float s_nrm[256];
    s_cls[tid] = cls;
    s_nrm[tid] = norm;
    __syncthreads();
    float4* sco4 = reinterpret_cast<float4*>(out + N1 * 5 + (size_t)blockIdx.x * 256 * NC);
    for (int idx = tid; idx < 256 * (NC / 4); idx += 256) {
        const int al = idx / (NC / 4);
        const int q  = idx - al * (NC / 4);
        const int c0 = q * 4;
        const int cl = s_cls[al];
        const float nv = s_nrm[al];
        float4 w = make_float4(0.0f, 0.0f, 0.0f, 0.0f);
        if (cl == c0)     w.x = nv;
        if (cl == c0 + 1) w.y = nv;
        if (cl == c0 + 2) w.z = nv;
        if (cl == c0 + 3) w.w = nv;
        __stcs(sco4 + idx, w);
    }
}

// ============================================================
extern "C" void kernel_launch(void* const* d_in, const int* in_sizes, int n_in,
                              void* d_out, int out_size)
{
    const float* pd_scores = (const float*)d_in[0];
    const float* pd_bboxes = (const float*)d_in[1];
    const float* anc       = (const float*)d_in[2];
    const int*   gl        = (const int*)d_in[3];
    const float* gb        = (const float*)d_in[4];
    const float* gm        = (const float*)d_in[5];
    float* out = (float*)d_out;

    kCount<<<CBLOCKS, 1024>>>(anc);
    kScan<<<1, 512>>>();
    kFill<<<(NA + 1023) / 1024, 1024>>>(anc);
    kmain<<<BS * NG, 128>>>(pd_scores, pd_bboxes, gl, gb, gm, anc);
    k4_final<<<(BS * NA) / 256, 256>>>(gl, gb, pd_bboxes, pd_scores, anc, gm, out);
}

// round 16
// speedup vs baseline: 1.4195x; 1.0115x over previous
#include <cuda_runtime.h>
#include <math.h>

#define BS 16
#define NA 8400
#define NG 128
#define NC 80
#define TOPK 13
#define CAPR 768             // per-row candidate capacity (max observed <=640 passes)
#define RPB 8                // rows per kTopk block

#define GRIDB 20             // bins per dim
#define BINW_INV (1.0f/32.0f)
#define NBINS (GRIDB*GRIDB)
#define MAXSEG 8             // max covered bin-rows (box <=144px -> <=6)

#define EPS9 1e-9f
#define EPS7 1e-7f
#define FOUR_OVER_PI2 0.4052847345693511f

// ---- scratch (__device__ globals; no allocation allowed) ----
// INVARIANT: g_bincnt == 0 at kernel_launch entry. True at process start
// (static zero-init); kScan consumes the counts and re-zeroes them.
__device__ int                g_bincnt[NBINS];
__device__ int                g_off   [NBINS];           // fill cursors (set by kScan)
__device__ int                g_binstart[NBINS + 1];
__device__ int                g_csridx[NA];              // anchor index per CSR slot
__device__ int                g_rowcnt[BS * NG];         // per-row candidate count
__device__ unsigned long long g_cand[(size_t)BS * NG * CAPR];
__device__ int                g_firstg[BS * NA];         // min marked g (init BIG)
__device__ int                g_acnt  [BS * NA];         // mark count
__device__ unsigned long long g_bestpack[BS * NA];       // (al_bits<<32)|(127-g)
__device__ int                g_anyflag;

#define FIRSTG_INIT 0x40000000

// CIoU clipped to [0,inf); identical op order in kCollect and K4.
__device__ __forceinline__ float ciou_clip(
    float b1x1, float b1y1, float b1x2, float b1y2,
    float b2x1, float b2y1, float b2x2, float b2y2)
{
    float iw = fminf(b1x2, b2x2) - fmaxf(b1x1, b2x1); iw = fmaxf(iw, 0.0f);
    float ih = fminf(b1y2, b2y2) - fmaxf(b1y1, b2y1); ih = fmaxf(ih, 0.0f);
    const float inter = iw * ih;
    const float w1 = b1x2 - b1x1, h1 = b1y2 - b1y1 + EPS7;
    const float w2 = b2x2 - b2x1, h2 = b2y2 - b2y1 + EPS7;
    const float uni = w1 * h1 + w2 * h2 - inter + EPS7;
    const float iou = inter / uni;
    const float cw = fmaxf(b1x2, b2x2) - fminf(b1x1, b2x1);
    const float ch = fmaxf(b1y2, b2y2) - fminf(b1y1, b2y1);
    const float c2 = cw * cw + ch * ch + EPS7;
    const float dx = b2x1 + b2x2 - b1x1 - b1x2;
    const float dy = b2y1 + b2y2 - b1y1 - b1y2;
    const float rho2 = (dx * dx + dy * dy) * 0.25f;
    const float dat = atanf(w2 / h2) - atanf(w1 / h1);
    const float v = FOUR_OVER_PI2 * dat * dat;
    const float alpha = v / (v - iou + (1.0f + EPS7));
    return fmaxf(iou - (rho2 / c2 + v * alpha), 0.0f);
}

__device__ __forceinline__ int bin_of(float x) {
    int b = (int)(x * BINW_INV);
    return (b < 0) ? 0 : ((b > GRIDB - 1) ? GRIDB - 1 : b);
}

// ============================================================
// K_COUNT: 132 blocks. Zero per-anchor + per-row state; first
// NA threads count anchors per bin via GLOBAL atomics.
// ============================================================
#define CBLOCKS ((BS * NA + 1023) / 1024)     // 132
#define SCAN_WARPS ((NBINS + 31) / 32)        // 13

__global__ void kCount(const float* __restrict__ anc_points)
{
    const int i = blockIdx.x * 1024 + threadIdx.x;
    if (i < BS * NA) {
        g_firstg[i]   = FIRSTG_INIT;
        g_acnt[i]     = 0;
        g_bestpack[i] = 127ULL;     // pack(0.0f, g=0)
    }
    if (i < BS * NG) g_rowcnt[i] = 0;
    if (i == 0) g_anyflag = 0;
    if (i < NA) {
        const float2 p = reinterpret_cast<const float2*>(anc_points)[i];
        atomicAdd(&g_bincnt[bin_of(p.y) * GRIDB + bin_of(p.x)], 1);
    }
}

// ============================================================
// K_SCAN: one tiny block (512 thr): two-level parallel scan of
// the 400 counters -> g_binstart + g_off; re-zero g_bincnt.
// ============================================================
__global__ void kScan()
{
    const int tid  = threadIdx.x;   // 512
    const int wid  = tid >> 5;
    const int lane = tid & 31;
    __shared__ int s_wsum[SCAN_WARPS];

    int cnt = 0, inc = 0;
    if (tid < (SCAN_WARPS * 32)) {
        cnt = (tid < NBINS) ? g_bincnt[tid] : 0;
        inc = cnt;
#pragma unroll
        for (int off = 1; off < 32; off <<= 1) {
            const int n = __shfl_up_sync(0xffffffffu, inc, off);
            if (lane >= off) inc += n;
        }
        if (lane == 31) s_wsum[wid] = inc;
    }
    __syncthreads();
    if (wid == 0) {
        int ws = (lane < SCAN_WARPS) ? s_wsum[lane] : 0;
        int wi = ws;
#pragma unroll
        for (int off = 1; off < 32; off <<= 1) {
            const int n = __shfl_up_sync(0xffffffffu, wi, off);
            if (lane >= off) wi += n;
        }
        if (lane < SCAN_WARPS) s_wsum[lane] = wi - ws;   // exclusive warp offset
    }
    __syncthreads();
    if (tid < NBINS) {
        const int excl = (inc - cnt) + s_wsum[wid];
        g_binstart[tid] = excl;
        g_off[tid]      = excl;
        g_bincnt[tid]   = 0;        // restore invariant (counts consumed)
    }
    if (tid == 0) g_binstart[NBINS] = NA;
}

// ============================================================
// K_FILL: global atomic cursors (order-invariant consumers).
// ============================================================
__global__ void kFill(const float* __restrict__ anc_points)
{
    const int a = blockIdx.x * 1024 + threadIdx.x;
    if (a >= NA) return;
    const float2 p = reinterpret_cast<const float2*>(anc_points)[a];
    const int bin = bin_of(p.y) * GRIDB + bin_of(p.x);
    const int q = atomicAdd(&g_off[bin], 1);
    g_csridx[q] = a;
}

// ============================================================
// K_COLLECT: one block (128 thr) per (b,g) row. Flattened
// segment gather; candidates pushed to GLOBAL per-row lists as
// packed u64 keys ((al_bits<<32)|~a). No top-k tail -> all
// warps busy to block end. best_gt via 64-bit atomicMax.
// ============================================================
__global__ void kCollect(const float* __restrict__ pd_scores,
                         const float* __restrict__ pd_bboxes,
                         const int*   __restrict__ gt_labels,
                         const float* __restrict__ gt_bboxes,
                         const float* __restrict__ gt_mask,
                         const float* __restrict__ anc_points)
{
    const int row = blockIdx.x;          // b*NG + g
    const int tid = threadIdx.x;         // 128
    const int b = row >> 7;
    const int g = row & (NG - 1);

    __shared__ int   s_seg_s[MAXSEG];
    __shared__ int   s_seg_p[MAXSEG + 1];
    __shared__ float4 s_box;
    __shared__ float  s_msk;
    __shared__ int    s_lbl;

    if (tid == 0) {
        s_box = reinterpret_cast<const float4*>(gt_bboxes)[(size_t)b * NG + g];
        s_msk = gt_mask[row];
        int l = gt_labels[row];
        s_lbl = (l < 0) ? 0 : ((l >= NC) ? NC - 1 : l);
        const float4 bb = s_box;
        const int bx0 = bin_of(bb.x), bx1 = bin_of(bb.z);
        const int by0 = bin_of(bb.y), by1 = bin_of(bb.w);
        int acc = 0, ns = 0;
        for (int by = by0; by <= by1 && ns < MAXSEG; by++, ns++) {
            const int s = g_binstart[by * GRIDB + bx0];
            const int e = g_binstart[by * GRIDB + bx1 + 1];
            s_seg_s[ns] = s;
            s_seg_p[ns] = acc;
            acc += e - s;
        }
        for (int k2 = ns; k2 <= MAXSEG; k2++) s_seg_p[k2] = acc;
    }
    __syncthreads();

    const float msk = s_msk;
    if (msk <= 0.0f) return;

    const float4 gbb = s_box;
    const int lbl = s_lbl;
    const int total = s_seg_p[MAXSEG];
    const float2* anc2 = reinterpret_cast<const float2*>(anc_points);
    unsigned long long* cand = g_cand + (size_t)row * CAPR;

    for (int t = tid; t < total; t += 128) {
        int r = 0;
#pragma unroll
        for (int k2 = 1; k2 < MAXSEG; k2++)
            if (t >= s_seg_p[k2]) r = k2;
        const int j = s_seg_s[r] + (t - s_seg_p[r]);

        const int a = g_csridx[j];
        const float2 p = anc2[a];
        const float d0 = p.x - gbb.x, d1 = p.y - gbb.y;
        const float d2 = gbb.z - p.x, d3 = gbb.w - p.y;
        const float dmin = fminf(fminf(d0, d1), fminf(d2, d3));
        if (dmin > EPS9) {
            const float4 pb = reinterpret_cast<const float4*>(pd_bboxes)[(size_t)b * NA + a];
            const float io = ciou_clip(pb.x, pb.y, pb.z, pb.w,
                                       gbb.x, gbb.y, gbb.z, gbb.w);
            const float sc = pd_scores[((size_t)b * NA + a) * NC + lbl];
            const float i2 = io * io;
            const float al = sc * (i2 * i2 * i2) * msk;
            if (al > 0.0f) {
                const unsigned long long pk =
                    ((unsigned long long)__float_as_uint(al) << 32) |
                    (unsigned long long)(127 - g);
                atomicMax(&g_bestpack[b * NA + a], pk);
            }
            if (al > EPS9) {
                const int pIdx = atomicAdd(&g_rowcnt[row], 1);
                if (pIdx < CAPR)
                    cand[pIdx] =
                        ((unsigned long long)__float_as_uint(al) << 32) |
                        (unsigned long long)(~(unsigned)a);
            }
        }
    }
}

// ============================================================
// K_TOPK: one WARP per row, 8 rows per 256-thread block
// (all 2048 rows' top-13 loops run concurrently). Candidates
// staged to smem once; 13 u64-max pops (max val, min anchor
// idx == lax.top_k order); marks issued in parallel by lanes.
// ============================================================
__global__ void kTopk()
{
    const int wid  = threadIdx.x >> 5;        // 0..7
    const int lane = threadIdx.x & 31;
    const int row  = blockIdx.x * RPB + wid;  // b*NG + g
    const int b = row >> 7;
    const int g = row & (NG - 1);

    __shared__ unsigned long long s_key[RPB][CAPR];   // 48 KB
    __shared__ unsigned long long s_win[RPB][TOPK];

    int cnt = g_rowcnt[row];                  // broadcast
    if (cnt <= 0) return;                     // warp-uniform
    if (cnt > CAPR) cnt = CAPR;

    const unsigned long long* cand = g_cand + (size_t)row * CAPR;
    for (int i = lane; i < cnt; i += 32)
        s_key[wid][i] = cand[i];
    __syncwarp();

    const int kmax = (TOPK < cnt) ? TOPK : cnt;
    for (int k = 0; k < kmax; k++) {
        unsigned long long bk = 0ULL;
        int bslot = -1;
        for (int i = lane; i < cnt; i += 32) {
            const unsigned long long key = s_key[wid][i];
            if (key > bk) { bk = key; bslot = i; }
        }
#pragma unroll
        for (int off = 16; off > 0; off >>= 1) {
            const unsigned long long ok = __shfl_down_sync(0xffffffffu, bk, off);
            const int os = __shfl_down_sync(0xffffffffu, bslot, off);
            if (ok > bk) { bk = ok; bslot = os; }
        }
        bslot = __shfl_sync(0xffffffffu, bslot, 0);
        if (lane == 0) {
            s_win[wid][k] = bk;
            s_key[wid][bslot] = 0ULL;
        }
        __syncwarp();
    }

    // parallel marks (order-invariant atomics)
    if (lane < kmax) {
        const unsigned long long bk = s_win[wid][lane];
        const int a = (int)(~(unsigned)(bk & 0xFFFFFFFFULL));
        atomicMin(&g_firstg[b * NA + a], g);
        const int old = atomicAdd(&g_acnt[b * NA + a], 1);
        if (old > 0) g_anyflag = 1;
    }
}

// ============================================================
// K4: per-anchor resolution + ALL outputs (fused; score write
// via smem staging, streaming stores).
// ============================================================
__global__ void k4_final(const int*   __restrict__ gt_labels,
                         const float* __restrict__ gt_bboxes,
                         const float* __restrict__ pd_bboxes,
                         const float* __restrict__ pd_scores,
                         const float* __restrict__ anc_points,
                         const float* __restrict__ gt_mask,
                         float* __restrict__ out)
{
    const int tid = threadIdx.x;                       // 256
    const int i   = blockIdx.x * 256 + tid;            // exact grid
    const int b   = i / NA;
    const int a   = i - b * NA;

    const int flag = g_anyflag;
    const int conf = (g_acnt[i] > 1);
    const int best = 127 - (int)(g_bestpack[i] & 0xFFULL);
    const int fg   = g_firstg[i];
    const int g0   = (fg >= FIRSTG_INIT) ? -1 : fg;

    int gA = -1, gB = -1; float vA = 0.0f, vB = 0.0f;
    if (flag) {
        if (!conf) {
            if (g0 < 0)          { gA = best; vA = 1.0f; }
            else if (g0 == best) { gA = g0;   vA = 2.0f; }
            else if (g0 < best)  { gA = g0; vA = 1.0f; gB = best; vB = 1.0f; }
            else                 { gA = best; vA = 1.0f; gB = g0; vB = 1.0f; }
        }
    } else {
        if (g0 >= 0) { gA = g0; vA = 1.0f; }
    }

    int tgt = 0;
    const int anyv = (gA >= 0);
    if (gA >= 0) tgt = gA;

    float maxamf = 0.0f, maxiou = 0.0f;
    if (anyv) {
        const float4 pb = reinterpret_cast<const float4*>(pd_bboxes)[(size_t)b * NA + a];
        const float ax = anc_points[a * 2 + 0];
        const float ay = anc_points[a * 2 + 1];
#pragma unroll
        for (int c = 0; c < 2; c++) {
            const int gc = (c == 0) ? gA : gB;
            const float vc = (c == 0) ? vA : vB;
            if (gc < 0) continue;
            const float4 gbb = reinterpret_cast<const float4*>(gt_bboxes)[(size_t)b * NG + gc];
            const float io = ciou_clip(pb.x, pb.y, pb.z, pb.w, gbb.x, gbb.y, gbb.z, gbb.w);
            int l = gt_labels[(size_t)b * NG + gc];
            l = (l < 0) ? 0 : ((l >= NC) ? NC - 1 : l);
            const float sc = pd_scores[((size_t)b * NA + a) * NC + l];
            const float d0 = ax - gbb.x, d1 = ay - gbb.y;
            const float d2 = gbb.z - ax, d3 = gbb.w - ay;
            const float dmin = fminf(fminf(d0, d1), fminf(d2, d3));
            const float mp = (dmin > EPS9) ? gt_mask[(size_t)b * NG + gc] : 0.0f;
            const float i2 = io * io;
            const float al = sc * (i2 * i2 * i2) * mp;
            maxamf = fmaxf(maxamf, al * vc);
            maxiou = fmaxf(maxiou, io * vc);
        }
    }
    const float norm = (maxamf * maxamf) / (maxiou + 1e-9f);
    const int   cls  = gt_labels[(size_t)b * NG + tgt];

    const size_t N1 = (size_t)BS * NA;
    out[i] = (float)cls;
    reinterpret_cast<float4*>(out + N1)[i] =
        reinterpret_cast<const float4*>(gt_bboxes)[(size_t)b * NG + tgt];
    const size_t off_mask = N1 * 5 + N1 * (size_t)NC;
    out[off_mask + i]      = anyv ? 1.0f : 0.0f;
    out[off_mask + N1 + i] = norm;

    // coalesced one-hot score write via smem staging; streaming stores
    __shared__ int   s_cls[256];
    __shared__ float s_nrm[256];
    s_cls[tid] = cls;
    s_nrm[tid] = norm;
    __syncthreads();
    float4* sco4 = reinterpret_cast<float4*>(out + N1 * 5 + (size_t)blockIdx.x * 256 * NC);
    for (int idx = tid; idx < 256 * (NC / 4); idx += 256) {
        const int al = idx / (NC / 4);
        const int q  = idx - al * (NC / 4);
        const int c0 = q * 4;
        const int cl = s_cls[al];
        const float nv = s_nrm[al];
        float4 w = make_float4(0.0f, 0.0f, 0.0f, 0.0f);
        if (cl == c0)     w.x = nv;
        if (cl == c0 + 1) w.y = nv;
        if (cl == c0 + 2) w.z = nv;
        if (cl == c0 + 3) w.w = nv;
        __stcs(sco4 + idx, w);
    }
}

// ============================================================
extern "C" void kernel_launch(void* const* d_in, const int* in_sizes, int n_in,
                              void* d_out, int out_size)
{
    const float* pd_scores = (const float*)d_in[0];
    const float* pd_bboxes = (const float*)d_in[1];
    const float* anc       = (const float*)d_in[2];
    const int*   gl        = (const int*)d_in[3];
    const float* gb        = (const float*)d_in[4];
    const float* gm        = (const float*)d_in[5];
    float* out = (float*)d_out;

    kCount<<<CBLOCKS, 1024>>>(anc);
    kScan<<<1, 512>>>();
    kFill<<<(NA + 1023) / 1024, 1024>>>(anc);
    kCollect<<<BS * NG, 128>>>(pd_scores, pd_bboxes, gl, gb, gm, anc);
    kTopk<<<(BS * NG) / RPB, 256>>>();
    k4_final<<<(BS * NA) / 256, 256>>>(gl, gb, pd_bboxes, pd_scores, anc, gm, out);
}

// round 17
// speedup vs baseline: 1.4790x; 1.0419x over previous
#include <cuda_runtime.h>
#include <math.h>

#define BS 16
#define NA 8400
#define NG 128
#define NC 80
#define TOPK 13
#define CAPR 768             // per-row candidate capacity (max observed <=640)
#define RPB 8                // rows per kTopk block

#define GRIDB 20             // bins per dim
#define BINW_INV (1.0f/32.0f)
#define NBINS (GRIDB*GRIDB)
#define MAXSEG 8             // max covered bin-rows (box <=144px -> <=6)

#define EPS9 1e-9f
#define EPS7 1e-7f
#define FOUR_OVER_PI2 0.4052847345693511f

// ---- scratch (__device__ globals; no allocation allowed) ----
// INVARIANT: g_bincnt == 0 at kernel_launch entry. True at process start
// (static zero-init); kScan consumes the counts and re-zeroes them.
__device__ int                g_bincnt[NBINS];
__device__ int                g_off   [NBINS];           // fill cursors (set by kScan)
__device__ int                g_binstart[NBINS + 1];
__device__ int                g_csridx[NA];              // anchor index per CSR slot
__device__ int                g_rowcnt[BS * NG];         // per-row candidate count
__device__ unsigned long long g_cand[(size_t)BS * NG * CAPR];
__device__ int                g_firstg[BS * NA];         // min marked g (init BIG)
__device__ int                g_acnt  [BS * NA];         // mark count
__device__ unsigned long long g_bestpack[BS * NA];       // (al_bits<<32)|(127-g)
__device__ int                g_anyflag;

#define FIRSTG_INIT 0x40000000

// CIoU clipped to [0,inf); identical op order in kCollect and K4.
__device__ __forceinline__ float ciou_clip(
    float b1x1, float b1y1, float b1x2, float b1y2,
    float b2x1, float b2y1, float b2x2, float b2y2)
{
    float iw = fminf(b1x2, b2x2) - fmaxf(b1x1, b2x1); iw = fmaxf(iw, 0.0f);
    float ih = fminf(b1y2, b2y2) - fmaxf(b1y1, b2y1); ih = fmaxf(ih, 0.0f);
    const float inter = iw * ih;
    const float w1 = b1x2 - b1x1, h1 = b1y2 - b1y1 + EPS7;
    const float w2 = b2x2 - b2x1, h2 = b2y2 - b2y1 + EPS7;
    const float uni = w1 * h1 + w2 * h2 - inter + EPS7;
    const float iou = inter / uni;
    const float cw = fmaxf(b1x2, b2x2) - fminf(b1x1, b2x1);
    const float ch = fmaxf(b1y2, b2y2) - fminf(b1y1, b2y1);
    const float c2 = cw * cw + ch * ch + EPS7;
    const float dx = b2x1 + b2x2 - b1x1 - b1x2;
    const float dy = b2y1 + b2y2 - b1y1 - b1y2;
    const float rho2 = (dx * dx + dy * dy) * 0.25f;
    const float dat = atanf(w2 / h2) - atanf(w1 / h1);
    const float v = FOUR_OVER_PI2 * dat * dat;
    const float alpha = v / (v - iou + (1.0f + EPS7));
    return fmaxf(iou - (rho2 / c2 + v * alpha), 0.0f);
}

__device__ __forceinline__ int bin_of(float x) {
    int b = (int)(x * BINW_INV);
    return (b < 0) ? 0 : ((b > GRIDB - 1) ? GRIDB - 1 : b);
}

// ============================================================
// K_COUNT: 132 blocks. Zero per-anchor + per-row state; first
// NA threads count anchors per bin via GLOBAL atomics.
// ============================================================
#define CBLOCKS ((BS * NA + 1023) / 1024)     // 132
#define SCAN_WARPS ((NBINS + 31) / 32)        // 13

__global__ void kCount(const float* __restrict__ anc_points)
{
    const int i = blockIdx.x * 1024 + threadIdx.x;
    if (i < BS * NA) {
        g_firstg[i]   = FIRSTG_INIT;
        g_acnt[i]     = 0;
        g_bestpack[i] = 127ULL;     // pack(0.0f, g=0)
    }
    if (i < BS * NG) g_rowcnt[i] = 0;
    if (i == 0) g_anyflag = 0;
    if (i < NA) {
        const float2 p = reinterpret_cast<const float2*>(anc_points)[i];
        atomicAdd(&g_bincnt[bin_of(p.y) * GRIDB + bin_of(p.x)], 1);
    }
}

// ============================================================
// K_SCAN: one tiny block (512 thr): two-level parallel scan of
// the 400 counters -> g_binstart + g_off; re-zero g_bincnt.
// ============================================================
__global__ void kScan()
{
    const int tid  = threadIdx.x;   // 512
    const int wid  = tid >> 5;
    const int lane = tid & 31;
    __shared__ int s_wsum[SCAN_WARPS];

    int cnt = 0, inc = 0;
    if (tid < (SCAN_WARPS * 32)) {
        cnt = (tid < NBINS) ? g_bincnt[tid] : 0;
        inc = cnt;
#pragma unroll
        for (int off = 1; off < 32; off <<= 1) {
            const int n = __shfl_up_sync(0xffffffffu, inc, off);
            if (lane >= off) inc += n;
        }
        if (lane == 31) s_wsum[wid] = inc;
    }
    __syncthreads();
    if (wid == 0) {
        int ws = (lane < SCAN_WARPS) ? s_wsum[lane] : 0;
        int wi = ws;
#pragma unroll
        for (int off = 1; off < 32; off <<= 1) {
            const int n = __shfl_up_sync(0xffffffffu, wi, off);
            if (lane >= off) wi += n;
        }
        if (lane < SCAN_WARPS) s_wsum[lane] = wi - ws;   // exclusive warp offset
    }
    __syncthreads();
    if (tid < NBINS) {
        const int excl = (inc - cnt) + s_wsum[wid];
        g_binstart[tid] = excl;
        g_off[tid]      = excl;
        g_bincnt[tid]   = 0;        // restore invariant (counts consumed)
    }
    if (tid == 0) g_binstart[NBINS] = NA;
}

// ============================================================
// K_FILL: global atomic cursors (order-invariant consumers).
// ============================================================
__global__ void kFill(const float* __restrict__ anc_points)
{
    const int a = blockIdx.x * 1024 + threadIdx.x;
    if (a >= NA) return;
    const float2 p = reinterpret_cast<const float2*>(anc_points)[a];
    const int bin = bin_of(p.y) * GRIDB + bin_of(p.x);
    const int q = atomicAdd(&g_off[bin], 1);
    g_csridx[q] = a;
}

// ============================================================
// K_COLLECT: one block (128 thr) per (b,g) row. Pipelined
// gather: next iteration's csridx prefetched; anc/pd_bboxes/
// pd_scores loaded UNCONDITIONALLY (addresses depend only on
// a) so all three fly in parallel. Candidates pushed to global
// per-row lists via warp-aggregated atomics as packed u64 keys.
// best_gt via 64-bit atomicMax. Order-invariant -> replayable.
// ============================================================
__global__ void kCollect(const float* __restrict__ pd_scores,
                         const float* __restrict__ pd_bboxes,
                         const int*   __restrict__ gt_labels,
                         const float* __restrict__ gt_bboxes,
                         const float* __restrict__ gt_mask,
                         const float* __restrict__ anc_points)
{
    const int row = blockIdx.x;          // b*NG + g
    const int tid = threadIdx.x;         // 128
    const int lane = tid & 31;
    const int b = row >> 7;
    const int g = row & (NG - 1);

    __shared__ int   s_seg_s[MAXSEG];
    __shared__ int   s_seg_p[MAXSEG + 1];
    __shared__ float4 s_box;
    __shared__ float  s_msk;
    __shared__ int    s_lbl;

    if (tid == 0) {
        s_box = reinterpret_cast<const float4*>(gt_bboxes)[(size_t)b * NG + g];
        s_msk = gt_mask[row];
        int l = gt_labels[row];
        s_lbl = (l < 0) ? 0 : ((l >= NC) ? NC - 1 : l);
        const float4 bb = s_box;
        const int bx0 = bin_of(bb.x), bx1 = bin_of(bb.z);
        const int by0 = bin_of(bb.y), by1 = bin_of(bb.w);
        int acc = 0, ns = 0;
        for (int by = by0; by <= by1 && ns < MAXSEG; by++, ns++) {
            const int s = g_binstart[by * GRIDB + bx0];
            const int e = g_binstart[by * GRIDB + bx1 + 1];
            s_seg_s[ns] = s;
            s_seg_p[ns] = acc;
            acc += e - s;
        }
        for (int k2 = ns; k2 <= MAXSEG; k2++) s_seg_p[k2] = acc;
    }
    __syncthreads();

    const float msk = s_msk;
    if (msk <= 0.0f) return;

    const float4 gbb = s_box;
    const int lbl = s_lbl;
    const int total = s_seg_p[MAXSEG];
    const float2* anc2 = reinterpret_cast<const float2*>(anc_points);
    unsigned long long* cand = g_cand + (size_t)row * CAPR;

    // csr slot for a given flat t
    auto slot_of = [&](int t) {
        int r = 0;
#pragma unroll
        for (int k2 = 1; k2 < MAXSEG; k2++)
            if (t >= s_seg_p[k2]) r = k2;
        return s_seg_s[r] + (t - s_seg_p[r]);
    };

    int aNext = (tid < total) ? g_csridx[slot_of(tid)] : -1;

    for (int t = tid; t < total; t += 128) {
        const int a = aNext;
        // prefetch next iteration's anchor index immediately
        const int tn = t + 128;
        aNext = (tn < total) ? g_csridx[slot_of(tn)] : -1;

        // all three loads issue in parallel (no inside-test gate)
        const float2 p  = anc2[a];
        const float4 pb = reinterpret_cast<const float4*>(pd_bboxes)[(size_t)b * NA + a];
        const float  sc = pd_scores[((size_t)b * NA + a) * NC + lbl];

        const float d0 = p.x - gbb.x, d1 = p.y - gbb.y;
        const float d2 = gbb.z - p.x, d3 = gbb.w - p.y;
        const float dmin = fminf(fminf(d0, d1), fminf(d2, d3));

        float al = 0.0f;
        if (dmin > EPS9) {
            const float io = ciou_clip(pb.x, pb.y, pb.z, pb.w,
                                       gbb.x, gbb.y, gbb.z, gbb.w);
            const float i2 = io * io;
            al = sc * (i2 * i2 * i2) * msk;
            if (al > 0.0f) {
                const unsigned long long pk =
                    ((unsigned long long)__float_as_uint(al) << 32) |
                    (unsigned long long)(127 - g);
                atomicMax(&g_bestpack[b * NA + a], pk);
            }
        }

        // warp-aggregated candidate push
        const bool isCand = (al > EPS9);
        const unsigned ball = __ballot_sync(0xffffffffu, isCand);
        if (ball) {
            const int leader = __ffs(ball) - 1;
            int base = 0;
            if (lane == leader) base = atomicAdd(&g_rowcnt[row], __popc(ball));
            base = __shfl_sync(0xffffffffu, base, leader);
            if (isCand) {
                const int pIdx = base + __popc(ball & ((1u << lane) - 1u));
                if (pIdx < CAPR)
                    cand[pIdx] =
                        ((unsigned long long)__float_as_uint(al) << 32) |
                        (unsigned long long)(~(unsigned)a);
            }
        }
    }
}

// ============================================================
// K_TOPK: one WARP per row, 8 rows per 256-thread block.
// Candidates staged to smem; 13 u64-max pops (max val, min
// anchor idx == lax.top_k order); marks issued in parallel.
// ============================================================
__global__ void kTopk()
{
    const int wid  = threadIdx.x >> 5;        // 0..7
    const int lane = threadIdx.x & 31;
    const int row  = blockIdx.x * RPB + wid;  // b*NG + g
    const int b = row >> 7;
    const int g = row & (NG - 1);

    __shared__ unsigned long long s_key[RPB][CAPR];   // 48 KB
    __shared__ unsigned long long s_win[RPB][TOPK];

    int cnt = g_rowcnt[row];                  // broadcast
    if (cnt <= 0) return;                     // warp-uniform
    if (cnt > CAPR) cnt = CAPR;

    const unsigned long long* cand = g_cand + (size_t)row * CAPR;
    for (int i = lane; i < cnt; i += 32)
        s_key[wid][i] = cand[i];
    __syncwarp();

    const int kmax = (TOPK < cnt) ? TOPK : cnt;
    for (int k = 0; k < kmax; k++) {
        unsigned long long bk = 0ULL;
        int bslot = -1;
        for (int i = lane; i < cnt; i += 32) {
            const unsigned long long key = s_key[wid][i];
            if (key > bk) { bk = key; bslot = i; }
        }
#pragma unroll
        for (int off = 16; off > 0; off >>= 1) {
            const unsigned long long ok = __shfl_down_sync(0xffffffffu, bk, off);
            const int os = __shfl_down_sync(0xffffffffu, bslot, off);
            if (ok > bk) { bk = ok; bslot = os; }
        }
        bslot = __shfl_sync(0xffffffffu, bslot, 0);
        if (lane == 0) {
            s_win[wid][k] = bk;
            s_key[wid][bslot] = 0ULL;
        }
        __syncwarp();
    }

    // parallel marks (order-invariant atomics)
    if (lane < kmax) {
        const unsigned long long bk = s_win[wid][lane];
        const int a = (int)(~(unsigned)(bk & 0xFFFFFFFFULL));
        atomicMin(&g_firstg[b * NA + a], g);
        const int old = atomicAdd(&g_acnt[b * NA + a], 1);
        if (old > 0) g_anyflag = 1;
    }
}

// ============================================================
// K4: per-anchor resolution + ALL outputs (fused; score write
// via smem staging, streaming stores).
// ============================================================
__global__ void k4_final(const int*   __restrict__ gt_labels,
                         const float* __restrict__ gt_bboxes,
                         const float* __restrict__ pd_bboxes,
                         const float* __restrict__ pd_scores,
                         const float* __restrict__ anc_points,
                         const float* __restrict__ gt_mask,
                         float* __restrict__ out)
{
    const int tid = threadIdx.x;                       // 256
    const int i   = blockIdx.x * 256 + tid;            // exact grid
    const int b   = i / NA;
    const int a   = i - b * NA;

    const int flag = g_anyflag;
    const int conf = (g_acnt[i] > 1);
    const int best = 127 - (int)(g_bestpack[i] & 0xFFULL);
    const int fg   = g_firstg[i];
    const int g0   = (fg >= FIRSTG_INIT) ? -1 : fg;

    int gA = -1, gB = -1; float vA = 0.0f, vB = 0.0f;
    if (flag) {
        if (!conf) {
            if (g0 < 0)          { gA = best; vA = 1.0f; }
            else if (g0 == best) { gA = g0;   vA = 2.0f; }
            else if (g0 < best)  { gA = g0; vA = 1.0f; gB = best; vB = 1.0f; }
            else                 { gA = best; vA = 1.0f; gB = g0; vB = 1.0f; }
        }
    } else {
        if (g0 >= 0) { gA = g0; vA = 1.0f; }
    }

    int tgt = 0;
    const int anyv = (gA >= 0);
    if (gA >= 0) tgt = gA;

    float maxamf = 0.0f, maxiou = 0.0f;
    if (anyv) {
        const float4 pb = reinterpret_cast<const float4*>(pd_bboxes)[(size_t)b * NA + a];
        const float ax = anc_points[a * 2 + 0];
        const float ay = anc_points[a * 2 + 1];
#pragma unroll
        for (int c = 0; c < 2; c++) {
            const int gc = (c == 0) ? gA : gB;
            const float vc = (c == 0) ? vA : vB;
            if (gc < 0) continue;
            const float4 gbb = reinterpret_cast<const float4*>(gt_bboxes)[(size_t)b * NG + gc];
            const float io = ciou_clip(pb.x, pb.y, pb.z, pb.w, gbb.x, gbb.y, gbb.z, gbb.w);
            int l = gt_labels[(size_t)b * NG + gc];
            l = (l < 0) ? 0 : ((l >= NC) ? NC - 1 : l);
            const float sc = pd_scores[((size_t)b * NA + a) * NC + l];
            const float d0 = ax - gbb.x, d1 = ay - gbb.y;
            const float d2 = gbb.z - ax, d3 = gbb.w - ay;
            const float dmin = fminf(fminf(d0, d1), fminf(d2, d3));
            const float mp = (dmin > EPS9) ? gt_mask[(size_t)b * NG + gc] : 0.0f;
            const float i2 = io * io;
            const float al = sc * (i2 * i2 * i2) * mp;
            maxamf = fmaxf(maxamf, al * vc);
            maxiou = fmaxf(maxiou, io * vc);
        }
    }
    const float norm = (maxamf * maxamf) / (maxiou + 1e-9f);
    const int   cls  = gt_labels[(size_t)b * NG + tgt];

    const size_t N1 = (size_t)BS * NA;
    out[i] = (float)cls;
    reinterpret_cast<float4*>(out + N1)[i] =
        reinterpret_cast<const float4*>(gt_bboxes)[(size_t)b * NG + tgt];
    const size_t off_mask = N1 * 5 + N1 * (size_t)NC;
    out[off_mask + i]      = anyv ? 1.0f : 0.0f;
    out[off_mask + N1 + i] = norm;

    // coalesced one-hot score write via smem staging; streaming stores
    __shared__ int   s_cls[256];
    __shared__ float s_nrm[256];
    s_cls[tid] = cls;
    s_nrm[tid] = norm;
    __syncthreads();
    float4* sco4 = reinterpret_cast<float4*>(out + N1 * 5 + (size_t)blockIdx.x * 256 * NC);
    for (int idx = tid; idx < 256 * (NC / 4); idx += 256) {
        const int al = idx / (NC / 4);
        const int q  = idx - al * (NC / 4);
        const int c0 = q * 4;
        const int cl = s_cls[al];
        const float nv = s_nrm[al];
        float4 w = make_float4(0.0f, 0.0f, 0.0f, 0.0f);
        if (cl == c0)     w.x = nv;
        if (cl == c0 + 1) w.y = nv;
        if (cl == c0 + 2) w.z = nv;
        if (cl == c0 + 3) w.w = nv;
        __stcs(sco4 + idx, w);
    }
}

// ============================================================
extern "C" void kernel_launch(void* const* d_in, const int* in_sizes, int n_in,
                              void* d_out, int out_size)
{
    const float* pd_scores = (const float*)d_in[0];
    const float* pd_bboxes = (const float*)d_in[1];
    const float* anc       = (const float*)d_in[2];
    const int*   gl        = (const int*)d_in[3];
    const float* gb        = (const float*)d_in[4];
    const float* gm        = (const float*)d_in[5];
    float* out = (float*)d_out;

    kCount<<<CBLOCKS, 1024>>>(anc);
    kScan<<<1, 512>>>();
    kFill<<<(NA + 1023) / 1024, 1024>>>(anc);
    kCollect<<<BS * NG, 128>>>(pd_scores, pd_bboxes, gl, gb, gm, anc);
    kTopk<<<(BS * NG) / RPB, 256>>>();
    k4_final<<<(BS * NA) / 256, 256>>>(gl, gb, pd_bboxes, pd_scores, anc, gm, out);
}